// round 2
// baseline (speedup 1.0000x reference)
#include <cuda_runtime.h>
#include <math.h>

// Problem constants
#define BB     2
#define NN     2048
#define DIM    1024
#define HH     16
#define DH     64
#define INNER  1024          // H*DH
#define ROWS   (BB*NN)       // 4096
#define NQKV   3072          // 3*INNER
#define LN_EPS   1e-5f
#define ATTN_EPS 1e-8f
#define SCALE    0.125f      // 64^-0.5

// Scratch (device globals: allocation-free per harness rules)
__device__ float g_xn[ROWS * DIM];
__device__ float g_q[BB * HH * NN * DH];
__device__ float g_k[BB * HH * NN * DH];
__device__ float g_v[BB * HH * NN * DH];
__device__ float g_o[ROWS * INNER];

// ---------------------------------------------------------------------------
// LayerNorm: one block per row of 1024 floats
// ---------------------------------------------------------------------------
__global__ void ln_kernel(const float* __restrict__ x,
                          const float* __restrict__ gamma,
                          const float* __restrict__ beta,
                          float* __restrict__ xn) {
    const int row = blockIdx.x;
    const int t   = threadIdx.x;          // 256 threads, 4 floats each
    const float4* xr = (const float4*)(x + (size_t)row * DIM);
    float4 v = xr[t];
    float s  = v.x + v.y + v.z + v.w;
    float sq = v.x*v.x + v.y*v.y + v.z*v.z + v.w*v.w;

    // warp reduce
    #pragma unroll
    for (int o = 16; o > 0; o >>= 1) {
        s  += __shfl_down_sync(0xffffffffu, s,  o);
        sq += __shfl_down_sync(0xffffffffu, sq, o);
    }
    __shared__ float ws[8], wq[8];
    __shared__ float s_mu, s_rstd;
    const int lane = t & 31, wid = t >> 5;
    if (lane == 0) { ws[wid] = s; wq[wid] = sq; }
    __syncthreads();
    if (t == 0) {
        float S = 0.f, Q = 0.f;
        #pragma unroll
        for (int i = 0; i < 8; i++) { S += ws[i]; Q += wq[i]; }
        float mu  = S * (1.0f / DIM);
        float var = Q * (1.0f / DIM) - mu * mu;
        s_mu = mu;
        s_rstd = rsqrtf(var + LN_EPS);
    }
    __syncthreads();
    const float mu = s_mu, rstd = s_rstd;
    float4 g = ((const float4*)gamma)[t];
    float4 b = ((const float4*)beta)[t];
    float4 o;
    o.x = (v.x - mu) * rstd * g.x + b.x;
    o.y = (v.y - mu) * rstd * g.y + b.y;
    o.z = (v.z - mu) * rstd * g.z + b.z;
    o.w = (v.w - mu) * rstd * g.w + b.w;
    ((float4*)(xn + (size_t)row * DIM))[t] = o;
}

// ---------------------------------------------------------------------------
// QKV GEMM: [4096,1024] @ [1024,3072], epilogue scatters into [B,H,N,DH]
// 64x64 tile, BK=16, 256 threads, 4x4 per thread
// ---------------------------------------------------------------------------
__global__ void gemm_qkv_kernel(const float* __restrict__ A,
                                const float* __restrict__ W,
                                float* __restrict__ Qo,
                                float* __restrict__ Ko,
                                float* __restrict__ Vo) {
    __shared__ float As[16][65];   // [k][m]
    __shared__ float Bs[16][65];   // [k][n]
    const int tid = threadIdx.x;
    const int tx = tid & 15, ty = tid >> 4;
    const int brow = blockIdx.y * 64;
    const int bcol = blockIdx.x * 64;
    const int ar = tid >> 2, ac = (tid & 3) * 4;     // A loader: 64 rows x 16 k
    const int br = tid >> 4, bc = (tid & 15) * 4;    // B loader: 16 k x 64 cols
    float acc[4][4] = {};

    for (int k0 = 0; k0 < DIM; k0 += 16) {
        float4 av = *(const float4*)(A + (size_t)(brow + ar) * DIM + k0 + ac);
        float4 bv = *(const float4*)(W + (size_t)(k0 + br) * NQKV + bcol + bc);
        As[ac + 0][ar] = av.x; As[ac + 1][ar] = av.y;
        As[ac + 2][ar] = av.z; As[ac + 3][ar] = av.w;
        Bs[br][bc + 0] = bv.x; Bs[br][bc + 1] = bv.y;
        Bs[br][bc + 2] = bv.z; Bs[br][bc + 3] = bv.w;
        __syncthreads();
        #pragma unroll
        for (int kk = 0; kk < 16; kk++) {
            float a0 = As[kk][ty*4+0], a1 = As[kk][ty*4+1];
            float a2 = As[kk][ty*4+2], a3 = As[kk][ty*4+3];
            float b0 = Bs[kk][tx*4+0], b1 = Bs[kk][tx*4+1];
            float b2 = Bs[kk][tx*4+2], b3 = Bs[kk][tx*4+3];
            acc[0][0] += a0*b0; acc[0][1] += a0*b1; acc[0][2] += a0*b2; acc[0][3] += a0*b3;
            acc[1][0] += a1*b0; acc[1][1] += a1*b1; acc[1][2] += a1*b2; acc[1][3] += a1*b3;
            acc[2][0] += a2*b0; acc[2][1] += a2*b1; acc[2][2] += a2*b2; acc[2][3] += a2*b3;
            acc[3][0] += a3*b0; acc[3][1] += a3*b1; acc[3][2] += a3*b2; acc[3][3] += a3*b3;
        }
        __syncthreads();
    }
    // scatter epilogue: col -> (part, h, d); row -> (b, n)
    #pragma unroll
    for (int i = 0; i < 4; i++) {
        const int r = brow + ty * 4 + i;
        const int bq = r >> 11;           // / 2048
        const int n  = r & 2047;
        #pragma unroll
        for (int j = 0; j < 4; j++) {
            const int c = bcol + tx * 4 + j;
            const int part  = c >> 10;
            const int inner = c & 1023;
            const int h = inner >> 6;
            const int d = inner & 63;
            const size_t idx = (((size_t)(bq * HH + h)) * NN + n) * DH + d;
            float* dst = (part == 0) ? Qo : ((part == 1) ? Ko : Vo);
            dst[idx] = acc[i][j];
        }
    }
}

// ---------------------------------------------------------------------------
// Attention: flash-style. Block = 64 queries of one (b,h). No max subtraction
// (matches reference: exp(scale*s), normalize by rowsum + eps).
// ---------------------------------------------------------------------------
__global__ void attn_kernel(const float* __restrict__ Q,
                            const float* __restrict__ K,
                            const float* __restrict__ V,
                            float* __restrict__ O) {
    extern __shared__ float sm[];
    float (*sQ)[65] = (float(*)[65])(sm);
    float (*sK)[65] = (float(*)[65])(sm + 64 * 65);
    float (*sV)[65] = (float(*)[65])(sm + 2 * 64 * 65);
    float (*sS)[65] = (float(*)[65])(sm + 3 * 64 * 65);

    const int tid = threadIdx.x;
    const int tx = tid & 15, ty = tid >> 4;
    const int qt = blockIdx.x;     // query tile 0..31
    const int h  = blockIdx.y;
    const int b  = blockIdx.z;
    const size_t base = ((size_t)(b * HH + h)) * NN * DH;
    const float* Qp = Q + base + (size_t)qt * 64 * DH;

    // load Q tile [64 x 64]
    for (int p = tid; p < 1024; p += 256) {
        float4 v = ((const float4*)Qp)[p];
        const int row = p >> 4, dc = (p & 15) * 4;
        sQ[row][dc] = v.x; sQ[row][dc+1] = v.y; sQ[row][dc+2] = v.z; sQ[row][dc+3] = v.w;
    }

    float acc[4][4] = {};
    float dsum[4] = {};

    for (int t0 = 0; t0 < NN; t0 += 64) {
        __syncthreads();  // protect sK/sV/sS from previous iteration
        const float* Kp = K + base + (size_t)t0 * DH;
        const float* Vp = V + base + (size_t)t0 * DH;
        for (int p = tid; p < 1024; p += 256) {
            float4 kv = ((const float4*)Kp)[p];
            float4 vv = ((const float4*)Vp)[p];
            const int row = p >> 4, dc = (p & 15) * 4;
            sK[row][dc] = kv.x; sK[row][dc+1] = kv.y; sK[row][dc+2] = kv.z; sK[row][dc+3] = kv.w;
            sV[row][dc] = vv.x; sV[row][dc+1] = vv.y; sV[row][dc+2] = vv.z; sV[row][dc+3] = vv.w;
        }
        __syncthreads();

        // S = Q @ K^T for this 64x64 tile
        float s[4][4] = {};
        #pragma unroll 8
        for (int d = 0; d < 64; d++) {
            float qv[4], kv[4];
            #pragma unroll
            for (int i = 0; i < 4; i++) qv[i] = sQ[ty*4+i][d];
            #pragma unroll
            for (int j = 0; j < 4; j++) kv[j] = sK[tx*4+j][d];
            #pragma unroll
            for (int i = 0; i < 4; i++)
                #pragma unroll
                for (int j = 0; j < 4; j++)
                    s[i][j] += qv[i] * kv[j];
        }
        #pragma unroll
        for (int i = 0; i < 4; i++) {
            #pragma unroll
            for (int j = 0; j < 4; j++) {
                float e = expf(s[i][j] * SCALE);
                sS[ty*4+i][tx*4+j] = e;
                dsum[i] += e;
            }
        }
        __syncthreads();

        // acc += expS @ V
        #pragma unroll 8
        for (int kk = 0; kk < 64; kk++) {
            float pv[4], vv[4];
            #pragma unroll
            for (int i = 0; i < 4; i++) pv[i] = sS[ty*4+i][kk];
            #pragma unroll
            for (int j = 0; j < 4; j++) vv[j] = sV[kk][tx*4+j];
            #pragma unroll
            for (int i = 0; i < 4; i++)
                #pragma unroll
                for (int j = 0; j < 4; j++)
                    acc[i][j] += pv[i] * vv[j];
        }
    }
    __syncthreads();

    // denom reduction: reuse sS as [row][tx] partials
    #pragma unroll
    for (int i = 0; i < 4; i++) sS[ty*4+i][tx] = dsum[i];
    __syncthreads();

    #pragma unroll
    for (int i = 0; i < 4; i++) {
        const int row = ty * 4 + i;
        float den = ATTN_EPS;
        #pragma unroll
        for (int t = 0; t < 16; t++) den += sS[row][t];
        const float inv = 1.0f / den;
        const int n = qt * 64 + row;
        float4 o4;
        o4.x = acc[i][0] * inv; o4.y = acc[i][1] * inv;
        o4.z = acc[i][2] * inv; o4.w = acc[i][3] * inv;
        *(float4*)(O + ((size_t)(b * NN + n)) * INNER + h * DH + tx * 4) = o4;
    }
}

// ---------------------------------------------------------------------------
// Output projection: [4096,1024] @ [1024,1024] + bias
// ---------------------------------------------------------------------------
__global__ void gemm_out_kernel(const float* __restrict__ A,
                                const float* __restrict__ W,
                                const float* __restrict__ bias,
                                float* __restrict__ C) {
    __shared__ float As[16][65];
    __shared__ float Bs[16][65];
    const int tid = threadIdx.x;
    const int tx = tid & 15, ty = tid >> 4;
    const int brow = blockIdx.y * 64;
    const int bcol = blockIdx.x * 64;
    const int ar = tid >> 2, ac = (tid & 3) * 4;
    const int br = tid >> 4, bc = (tid & 15) * 4;
    float acc[4][4] = {};

    for (int k0 = 0; k0 < INNER; k0 += 16) {
        float4 av = *(const float4*)(A + (size_t)(brow + ar) * INNER + k0 + ac);
        float4 bv = *(const float4*)(W + (size_t)(k0 + br) * DIM + bcol + bc);
        As[ac + 0][ar] = av.x; As[ac + 1][ar] = av.y;
        As[ac + 2][ar] = av.z; As[ac + 3][ar] = av.w;
        Bs[br][bc + 0] = bv.x; Bs[br][bc + 1] = bv.y;
        Bs[br][bc + 2] = bv.z; Bs[br][bc + 3] = bv.w;
        __syncthreads();
        #pragma unroll
        for (int kk = 0; kk < 16; kk++) {
            float a0 = As[kk][ty*4+0], a1 = As[kk][ty*4+1];
            float a2 = As[kk][ty*4+2], a3 = As[kk][ty*4+3];
            float b0 = Bs[kk][tx*4+0], b1 = Bs[kk][tx*4+1];
            float b2 = Bs[kk][tx*4+2], b3 = Bs[kk][tx*4+3];
            acc[0][0] += a0*b0; acc[0][1] += a0*b1; acc[0][2] += a0*b2; acc[0][3] += a0*b3;
            acc[1][0] += a1*b0; acc[1][1] += a1*b1; acc[1][2] += a1*b2; acc[1][3] += a1*b3;
            acc[2][0] += a2*b0; acc[2][1] += a2*b1; acc[2][2] += a2*b2; acc[2][3] += a2*b3;
            acc[3][0] += a3*b0; acc[3][1] += a3*b1; acc[3][2] += a3*b2; acc[3][3] += a3*b3;
        }
        __syncthreads();
    }
    #pragma unroll
    for (int i = 0; i < 4; i++) {
        const int r = brow + ty * 4 + i;
        const int c = bcol + tx * 4;
        float4 o4;
        o4.x = acc[i][0] + bias[c + 0];
        o4.y = acc[i][1] + bias[c + 1];
        o4.z = acc[i][2] + bias[c + 2];
        o4.w = acc[i][3] + bias[c + 3];
        *(float4*)(C + (size_t)r * DIM + c) = o4;
    }
}

// ---------------------------------------------------------------------------
extern "C" void kernel_launch(void* const* d_in, const int* in_sizes, int n_in,
                              void* d_out, int out_size) {
    const float* x      = (const float*)d_in[0];
    const float* gamma  = (const float*)d_in[1];
    const float* beta   = (const float*)d_in[2];
    const float* w_qkv  = (const float*)d_in[3];
    const float* w_out  = (const float*)d_in[4];
    const float* b_out  = (const float*)d_in[5];
    float* out = (float*)d_out;

    float *xn, *q, *k, *v, *o;
    cudaGetSymbolAddress((void**)&xn, g_xn);
    cudaGetSymbolAddress((void**)&q,  g_q);
    cudaGetSymbolAddress((void**)&k,  g_k);
    cudaGetSymbolAddress((void**)&v,  g_v);
    cudaGetSymbolAddress((void**)&o,  g_o);

    const int attn_smem = 4 * 64 * 65 * sizeof(float);  // 66560
    cudaFuncSetAttribute(attn_kernel, cudaFuncAttributeMaxDynamicSharedMemorySize, attn_smem);

    ln_kernel<<<ROWS, 256>>>(x, gamma, beta, xn);
    gemm_qkv_kernel<<<dim3(NQKV / 64, ROWS / 64), 256>>>(xn, w_qkv, q, k, v);
    attn_kernel<<<dim3(NN / 64, HH, BB), 256, attn_smem>>>(q, k, v, o);
    gemm_out_kernel<<<dim3(DIM / 64, ROWS / 64), 256>>>(o, w_out, b_out, out);
}

// round 5
// speedup vs baseline: 3.9994x; 3.9994x over previous
#include <cuda_runtime.h>
#include <cuda_bf16.h>
#include <math.h>
#include <stdint.h>

typedef __nv_bfloat16 bf16;

#define BB     2
#define NN     2048
#define DIM    1024
#define HH     16
#define DH     64
#define INNER  1024
#define ROWS   (BB*NN)       // 4096
#define NQKV   3072
#define KD     1024
#define LN_EPS   1e-5f
#define ATTN_EPS 1e-8f
#define SCALE    0.125f

// ---------------------------------------------------------------------------
// Scratch (device globals)
// ---------------------------------------------------------------------------
__device__ bf16 g_xn_hi[ROWS * DIM];
__device__ bf16 g_xn_lo[ROWS * DIM];
__device__ bf16 g_wqT_hi[NQKV * KD];
__device__ bf16 g_wqT_lo[NQKV * KD];
__device__ bf16 g_woT_hi[DIM * KD];
__device__ bf16 g_woT_lo[DIM * KD];
__device__ bf16 g_q_hi[BB*HH*NN*DH];
__device__ bf16 g_q_lo[BB*HH*NN*DH];
__device__ bf16 g_k_hi[BB*HH*NN*DH];
__device__ bf16 g_k_lo[BB*HH*NN*DH];
__device__ bf16 g_v_hi[BB*HH*NN*DH];
__device__ bf16 g_v_lo[BB*HH*NN*DH];
__device__ bf16 g_o_hi[ROWS * INNER];
__device__ bf16 g_o_lo[ROWS * INNER];

// ---------------------------------------------------------------------------
// Helpers
// ---------------------------------------------------------------------------
__device__ __forceinline__ uint32_t smem_u32(const void* p) {
    uint32_t a;
    asm("{ .reg .u64 t; cvta.to.shared.u64 t, %1; cvt.u32.u64 %0, t; }" : "=r"(a) : "l"(p));
    return a;
}
#define SWZ128(x) ((x) ^ (((x) >> 3) & 0x70))

__device__ __forceinline__ void cp16(uint32_t dst, const void* src) {
    size_t g = __cvta_generic_to_global(src);
    asm volatile("cp.async.cg.shared.global [%0], [%1], 16;" :: "r"(dst), "l"(g) : "memory");
}
__device__ __forceinline__ void cp_commit() { asm volatile("cp.async.commit_group;" ::: "memory"); }
__device__ __forceinline__ void cp_wait0()  { asm volatile("cp.async.wait_group 0;"  ::: "memory"); }
__device__ __forceinline__ void cp_wait1()  { asm volatile("cp.async.wait_group 1;"  ::: "memory"); }

__device__ __forceinline__ void ldsm4(uint32_t* r, uint32_t a) {
    asm volatile("ldmatrix.sync.aligned.m8n8.x4.shared.b16 {%0,%1,%2,%3}, [%4];"
        : "=r"(r[0]),"=r"(r[1]),"=r"(r[2]),"=r"(r[3]) : "r"(a));
}
__device__ __forceinline__ void ldsm4t(uint32_t* r, uint32_t a) {
    asm volatile("ldmatrix.sync.aligned.m8n8.x4.trans.shared.b16 {%0,%1,%2,%3}, [%4];"
        : "=r"(r[0]),"=r"(r[1]),"=r"(r[2]),"=r"(r[3]) : "r"(a));
}
__device__ __forceinline__ void mma16816(float* c, const uint32_t* a, const uint32_t* b) {
    asm volatile("mma.sync.aligned.m16n8k16.row.col.f32.bf16.bf16.f32 "
        "{%0,%1,%2,%3}, {%4,%5,%6,%7}, {%8,%9}, {%0,%1,%2,%3};"
        : "+f"(c[0]),"+f"(c[1]),"+f"(c[2]),"+f"(c[3])
        : "r"(a[0]),"r"(a[1]),"r"(a[2]),"r"(a[3]), "r"(b[0]),"r"(b[1]));
}
__device__ __forceinline__ uint32_t pack2(float x, float y) {
    __nv_bfloat162 t = __floats2bfloat162_rn(x, y);
    return *(uint32_t*)&t;
}
__device__ __forceinline__ float bhi(float v) {
    return __bfloat162float(__float2bfloat16(v));
}
__device__ __forceinline__ void f2hl(float v, bf16& h, bf16& l) {
    h = __float2bfloat16(v);
    l = __float2bfloat16(v - __bfloat162float(h));
}

// ---------------------------------------------------------------------------
// LayerNorm -> bf16 hi/lo
// ---------------------------------------------------------------------------
__global__ void ln_split_kernel(const float* __restrict__ x,
                                const float* __restrict__ gamma,
                                const float* __restrict__ beta,
                                bf16* __restrict__ xh, bf16* __restrict__ xl) {
    const int row = blockIdx.x;
    const int t   = threadIdx.x;
    float4 v = ((const float4*)(x + (size_t)row * DIM))[t];
    float s  = v.x + v.y + v.z + v.w;
    float sq = v.x*v.x + v.y*v.y + v.z*v.z + v.w*v.w;
    #pragma unroll
    for (int o = 16; o > 0; o >>= 1) {
        s  += __shfl_down_sync(0xffffffffu, s,  o);
        sq += __shfl_down_sync(0xffffffffu, sq, o);
    }
    __shared__ float ws[8], wq[8], s_mu, s_rstd;
    const int lane = t & 31, wid = t >> 5;
    if (lane == 0) { ws[wid] = s; wq[wid] = sq; }
    __syncthreads();
    if (t == 0) {
        float S = 0.f, Q = 0.f;
        #pragma unroll
        for (int i = 0; i < 8; i++) { S += ws[i]; Q += wq[i]; }
        float mu = S * (1.0f / DIM);
        float var = Q * (1.0f / DIM) - mu * mu;
        s_mu = mu; s_rstd = rsqrtf(var + LN_EPS);
    }
    __syncthreads();
    const float mu = s_mu, rstd = s_rstd;
    float4 g = ((const float4*)gamma)[t];
    float4 b = ((const float4*)beta)[t];
    float y0 = (v.x-mu)*rstd*g.x + b.x, y1 = (v.y-mu)*rstd*g.y + b.y;
    float y2 = (v.z-mu)*rstd*g.z + b.z, y3 = (v.w-mu)*rstd*g.w + b.w;
    bf16 h0,h1,h2,h3,l0,l1,l2,l3;
    f2hl(y0,h0,l0); f2hl(y1,h1,l1); f2hl(y2,h2,l2); f2hl(y3,h3,l3);
    __nv_bfloat162* H = (__nv_bfloat162*)(xh + (size_t)row * DIM);
    __nv_bfloat162* L = (__nv_bfloat162*)(xl + (size_t)row * DIM);
    H[2*t]   = __halves2bfloat162(h0,h1);  H[2*t+1] = __halves2bfloat162(h2,h3);
    L[2*t]   = __halves2bfloat162(l0,l1);  L[2*t+1] = __halves2bfloat162(l2,l3);
}

// ---------------------------------------------------------------------------
// W[K][N] f32 -> WT hi/lo [N][K] bf16
// ---------------------------------------------------------------------------
__global__ void transpose_split_kernel(const float* __restrict__ W,
                                       bf16* __restrict__ Th, bf16* __restrict__ Tl,
                                       int Kd, int Nd) {
    __shared__ float t[32][33];
    const int n0 = blockIdx.x * 32, k0 = blockIdx.y * 32;
    const int tx = threadIdx.x, ty = threadIdx.y;
    #pragma unroll
    for (int i = 0; i < 32; i += 8)
        t[ty + i][tx] = W[(size_t)(k0 + ty + i) * Nd + n0 + tx];
    __syncthreads();
    #pragma unroll
    for (int i = 0; i < 32; i += 8) {
        float v = t[tx][ty + i];
        bf16 h, l; f2hl(v, h, l);
        const size_t idx = (size_t)(n0 + ty + i) * Kd + k0 + tx;
        Th[idx] = h; Tl[idx] = l;
    }
}

// ---------------------------------------------------------------------------
// mma.sync split-bf16 GEMM: C[128 x 128] tile, BK=64, double-buffered cp.async.
// A [M][K] row-major hi/lo ; B [N][K] row-major-by-N hi/lo (i.e. B^T).
// EPI 0: write q/k/v bf16 hi/lo in [b,h,n,d]. EPI 1: +bias, f32 out.
// ---------------------------------------------------------------------------
#define GBK      64
#define GTILE_B  16384                 // 128 x 64 bf16
#define GBUF_B   (4*GTILE_B)           // Ah,Al,Bh,Bl
#define GEMM_SMEM (2*GBUF_B)           // 131072

template<int EPI>
__global__ void __launch_bounds__(256, 1)
gemm_mma_kernel(const bf16* __restrict__ Ah, const bf16* __restrict__ Al,
                const bf16* __restrict__ Bh, const bf16* __restrict__ Bl,
                bf16* __restrict__ qh, bf16* __restrict__ ql,
                bf16* __restrict__ kh, bf16* __restrict__ kl,
                bf16* __restrict__ vh, bf16* __restrict__ vl,
                const float* __restrict__ bias, float* __restrict__ outf) {
    extern __shared__ char smem[];
    const uint32_t sb = smem_u32(smem);
    const int tid = threadIdx.x;
    const int w = tid >> 5, lane = tid & 31;
    const int wm = w >> 2, wn = w & 3;          // 2 x 4 warp grid
    const int brow = blockIdx.y * 128;
    const int bcol = blockIdx.x * 128;

    const bf16* bases[4] = { Ah + (size_t)brow * KD, Al + (size_t)brow * KD,
                             Bh + (size_t)bcol * KD, Bl + (size_t)bcol * KD };

    auto load_chunk = [&](int buf, int k0) {
        const uint32_t bb = sb + buf * GBUF_B;
        #pragma unroll
        for (int i = 0; i < 16; i++) {
            const int arr = i >> 2;
            const int rem = tid + (i & 3) * 256;      // 0..1023
            const int row = rem >> 3, c = rem & 7;
            cp16(bb + arr * GTILE_B + SWZ128(row * 128 + c * 16),
                 bases[arr] + (size_t)row * KD + k0 + c * 8);
        }
        cp_commit();
    };

    float acc[4][4][4] = {};
    load_chunk(0, 0);

    for (int ch = 0; ch < KD / GBK; ch++) {
        const int cur = ch & 1;
        if (ch + 1 < KD / GBK) { load_chunk(cur ^ 1, (ch + 1) * GBK); cp_wait1(); }
        else                   { cp_wait0(); }
        __syncthreads();
        const uint32_t bb = sb + cur * GBUF_B;

        #pragma unroll
        for (int ks = 0; ks < 4; ks++) {
            const int k0 = ks * 16;
            // A fragments (hi/lo): 4 m-tiles of 16
            uint32_t Af[2][4][4];
            #pragma unroll
            for (int mf = 0; mf < 4; mf++) {
                const int arow = wm*64 + mf*16 + (lane & 15);
                const int acol = k0 + ((lane >> 4) << 3);
                const uint32_t ad = bb + SWZ128(arow * 128 + acol * 2);
                ldsm4(Af[0][mf], ad);
                ldsm4(Af[1][mf], ad + GTILE_B);
            }
            // B fragments (hi/lo): 2 x4 loads cover n32 x k16
            uint32_t Bf[2][2][4];
            #pragma unroll
            for (int bt = 0; bt < 2; bt++) {
                const int n0 = wn*32 + bt*16;
                const int grp = lane >> 3, r = lane & 7;
                const int brw = n0 + r + ((grp & 2) ? 8 : 0);
                const int bcl = k0 + ((grp & 1) ? 8 : 0);
                const uint32_t bd = bb + 2*GTILE_B + SWZ128(brw * 128 + bcl * 2);
                ldsm4(Bf[0][bt], bd);
                ldsm4(Bf[1][bt], bd + GTILE_B);
            }
            #pragma unroll
            for (int mf = 0; mf < 4; mf++) {
                #pragma unroll
                for (int nf = 0; nf < 4; nf++) {
                    const uint32_t* bh2 = &Bf[0][nf >> 1][(nf & 1) * 2];
                    const uint32_t* bl2 = &Bf[1][nf >> 1][(nf & 1) * 2];
                    mma16816(acc[mf][nf], Af[0][mf], bh2);
                    mma16816(acc[mf][nf], Af[0][mf], bl2);
                    mma16816(acc[mf][nf], Af[1][mf], bh2);
                }
            }
        }
        __syncthreads();
    }

    // Epilogue
    const int t4 = lane >> 2, t2 = (lane & 3) * 2;
    if (EPI == 0) {
        const int part = bcol >> 10;
        bf16* dh = (part == 0) ? qh : (part == 1) ? kh : vh;
        bf16* dl = (part == 0) ? ql : (part == 1) ? kl : vl;
        #pragma unroll
        for (int mf = 0; mf < 4; mf++) {
            #pragma unroll
            for (int nf = 0; nf < 4; nf++) {
                const int c0 = bcol + wn*32 + nf*8 + t2;
                const int inner = c0 & 1023;
                const int hh_ = inner >> 6, d = inner & 63;
                #pragma unroll
                for (int rr = 0; rr < 2; rr++) {
                    const int m = brow + wm*64 + mf*16 + t4 + rr*8;
                    const int bq = m >> 11, n = m & 2047;
                    const size_t idx = (((size_t)(bq*HH + hh_))*NN + n)*DH + d;
                    float v0 = acc[mf][nf][rr*2], v1 = acc[mf][nf][rr*2+1];
                    float h0 = bhi(v0), h1 = bhi(v1);
                    *(uint32_t*)(dh + idx) = pack2(v0, v1);
                    *(uint32_t*)(dl + idx) = pack2(v0 - h0, v1 - h1);
                }
            }
        }
    } else {
        #pragma unroll
        for (int mf = 0; mf < 4; mf++) {
            #pragma unroll
            for (int nf = 0; nf < 4; nf++) {
                const int c0 = bcol + wn*32 + nf*8 + t2;
                #pragma unroll
                for (int rr = 0; rr < 2; rr++) {
                    const int m = brow + wm*64 + mf*16 + t4 + rr*8;
                    float2 o2;
                    o2.x = acc[mf][nf][rr*2]   + bias[c0];
                    o2.y = acc[mf][nf][rr*2+1] + bias[c0+1];
                    *(float2*)(outf + (size_t)m * DIM + c0) = o2;
                }
            }
        }
    }
}

// ---------------------------------------------------------------------------
// Attention: FA2-style mma.sync, split-bf16. CTA = 128 queries of one (b,h).
// 8 warps x 16 q-rows. KV tiles of 64 keys, double-buffered.
// ---------------------------------------------------------------------------
#define ATILE_B   8192          // 64 x 64 bf16
#define ABUF_B    (4*ATILE_B)   // Kh,Kl,Vh,Vl = 32KB
#define ATTN_SMEM (2*ABUF_B)    // 64KB (Q staged in buf region first)

__global__ void __launch_bounds__(256, 1)
attn_mma_kernel(const bf16* __restrict__ Qh, const bf16* __restrict__ Ql,
                const bf16* __restrict__ Kh, const bf16* __restrict__ Kl,
                const bf16* __restrict__ Vh, const bf16* __restrict__ Vl,
                bf16* __restrict__ Ohi, bf16* __restrict__ Olo) {
    extern __shared__ char smem[];
    const uint32_t sb = smem_u32(smem);
    const int tid = threadIdx.x;
    const int w = tid >> 5, lane = tid & 31;
    const int qt = blockIdx.x, hh_ = blockIdx.y, bq = blockIdx.z;
    const size_t hb = ((size_t)(bq*HH + hh_)) * NN * DH;

    // ---- Stage Q tile (128 x 64 hi/lo) into smem, extract A-fragments ----
    {
        const bf16* qsrc[2] = { Qh + hb + (size_t)qt*128*DH, Ql + hb + (size_t)qt*128*DH };
        #pragma unroll
        for (int i = 0; i < 8; i++) {
            const int arr = i >> 2;
            const int rem = tid + (i & 3) * 256;      // 0..1023
            const int row = rem >> 3, c = rem & 7;
            cp16(sb + arr * 16384 + SWZ128(row * 128 + c * 16),
                 qsrc[arr] + (size_t)row * DH + c * 8);
        }
        cp_commit(); cp_wait0();
    }
    __syncthreads();
    uint32_t qf[2][4][4];                 // [hi/lo][ks][reg]
    #pragma unroll
    for (int ks = 0; ks < 4; ks++) {
        const int row = w*16 + (lane & 15);
        const int col = ks*16 + ((lane >> 4) << 3);
        const uint32_t ad = sb + SWZ128(row * 128 + col * 2);
        ldsm4(qf[0][ks], ad);
        ldsm4(qf[1][ks], ad + 16384);
    }
    __syncthreads();   // done with Q staging; region reused as KV buf0

    const bf16* kb[4] = { Kh + hb, Kl + hb, Vh + hb, Vl + hb };
    auto load_tile = [&](int buf, int s0) {
        const uint32_t bb = sb + buf * ABUF_B;
        #pragma unroll
        for (int i = 0; i < 8; i++) {
            const int arr = i >> 1;
            const int rem = tid + (i & 1) * 256;      // 0..511
            const int row = rem >> 3, c = rem & 7;
            cp16(bb + arr * ATILE_B + SWZ128(row * 128 + c * 16),
                 kb[arr] + (size_t)(s0 + row) * DH + c * 8);
        }
        cp_commit();
    };

    float oacc[8][4] = {};
    float dsum0 = 0.f, dsum1 = 0.f;

    load_tile(0, 0);
    for (int t = 0; t < NN/64; t++) {
        const int cur = t & 1;
        if (t + 1 < NN/64) { load_tile(cur ^ 1, (t + 1) * 64); cp_wait1(); }
        else               { cp_wait0(); }
        __syncthreads();
        const uint32_t bb = sb + cur * ABUF_B;

        // ---- S = Q K^T (64 keys) ----
        float sacc[8][4] = {};
        #pragma unroll
        for (int ks = 0; ks < 4; ks++) {
            uint32_t Kf[2][4][4];
            #pragma unroll
            for (int p = 0; p < 4; p++) {
                const int grp = lane >> 3, r = lane & 7;
                const int brw = p*16 + r + ((grp & 2) ? 8 : 0);
                const int bcl = ks*16 + ((grp & 1) ? 8 : 0);
                const uint32_t ad = bb + SWZ128(brw * 128 + bcl * 2);
                ldsm4(Kf[0][p], ad);
                ldsm4(Kf[1][p], ad + ATILE_B);
            }
            #pragma unroll
            for (int nt = 0; nt < 8; nt++) {
                const uint32_t* bh2 = &Kf[0][nt >> 1][(nt & 1) * 2];
                const uint32_t* bl2 = &Kf[1][nt >> 1][(nt & 1) * 2];
                mma16816(sacc[nt], qf[0][ks], bh2);
                mma16816(sacc[nt], qf[0][ks], bl2);
                mma16816(sacc[nt], qf[1][ks], bh2);
            }
        }

        // ---- exp + split into P A-fragments (in registers) ----
        uint32_t pf[2][4][4];                 // [hi/lo][j(k16)][reg]
        #pragma unroll
        for (int j = 0; j < 4; j++) {
            float pA[4], pB[4];
            #pragma unroll
            for (int e = 0; e < 4; e++) { pA[e] = __expf(sacc[2*j][e]   * SCALE); }
            #pragma unroll
            for (int e = 0; e < 4; e++) { pB[e] = __expf(sacc[2*j+1][e] * SCALE); }
            dsum0 += pA[0] + pA[1] + pB[0] + pB[1];
            dsum1 += pA[2] + pA[3] + pB[2] + pB[3];
            pf[0][j][0] = pack2(pA[0], pA[1]);
            pf[0][j][1] = pack2(pA[2], pA[3]);
            pf[0][j][2] = pack2(pB[0], pB[1]);
            pf[0][j][3] = pack2(pB[2], pB[3]);
            pf[1][j][0] = pack2(pA[0]-bhi(pA[0]), pA[1]-bhi(pA[1]));
            pf[1][j][1] = pack2(pA[2]-bhi(pA[2]), pA[3]-bhi(pA[3]));
            pf[1][j][2] = pack2(pB[0]-bhi(pB[0]), pB[1]-bhi(pB[1]));
            pf[1][j][3] = pack2(pB[2]-bhi(pB[2]), pB[3]-bhi(pB[3]));
        }

        // ---- O += P V ----
        #pragma unroll
        for (int j = 0; j < 4; j++) {
            uint32_t Vf[2][4][4];
            #pragma unroll
            for (int p = 0; p < 4; p++) {
                const int grp = lane >> 3, r = lane & 7;
                const int vrow = j*16 + r + ((grp & 1) ? 8 : 0);
                const int vcol = p*16 + ((grp & 2) ? 8 : 0);
                const uint32_t ad = bb + 2*ATILE_B + SWZ128(vrow * 128 + vcol * 2);
                ldsm4t(Vf[0][p], ad);
                ldsm4t(Vf[1][p], ad + ATILE_B);
            }
            #pragma unroll
            for (int nt = 0; nt < 8; nt++) {
                const uint32_t* bh2 = &Vf[0][nt >> 1][(nt & 1) * 2];
                const uint32_t* bl2 = &Vf[1][nt >> 1][(nt & 1) * 2];
                mma16816(oacc[nt], pf[0][j], bh2);
                mma16816(oacc[nt], pf[0][j], bl2);
                mma16816(oacc[nt], pf[1][j], bh2);
            }
        }
        __syncthreads();
    }

    // ---- normalize + store hi/lo bf16 [b, n, h*64+d] ----
    dsum0 += __shfl_xor_sync(0xffffffffu, dsum0, 1);
    dsum0 += __shfl_xor_sync(0xffffffffu, dsum0, 2);
    dsum1 += __shfl_xor_sync(0xffffffffu, dsum1, 1);
    dsum1 += __shfl_xor_sync(0xffffffffu, dsum1, 2);
    const float inv0 = 1.0f / (dsum0 + ATTN_EPS);
    const float inv1 = 1.0f / (dsum1 + ATTN_EPS);

    const int t4 = lane >> 2, t2 = (lane & 3) * 2;
    #pragma unroll
    for (int nf = 0; nf < 8; nf++) {
        const int d = nf*8 + t2;
        const int n0 = qt*128 + w*16 + t4;
        float v00 = oacc[nf][0]*inv0, v01 = oacc[nf][1]*inv0;
        float v10 = oacc[nf][2]*inv1, v11 = oacc[nf][3]*inv1;
        const size_t i0 = ((size_t)(bq*NN + n0)    )*INNER + hh_*DH + d;
        const size_t i1 = ((size_t)(bq*NN + n0 + 8))*INNER + hh_*DH + d;
        *(uint32_t*)(Ohi + i0) = pack2(v00, v01);
        *(uint32_t*)(Olo + i0) = pack2(v00 - bhi(v00), v01 - bhi(v01));
        *(uint32_t*)(Ohi + i1) = pack2(v10, v11);
        *(uint32_t*)(Olo + i1) = pack2(v10 - bhi(v10), v11 - bhi(v11));
    }
}

// ---------------------------------------------------------------------------
extern "C" void kernel_launch(void* const* d_in, const int* in_sizes, int n_in,
                              void* d_out, int out_size) {
    const float* x      = (const float*)d_in[0];
    const float* gamma  = (const float*)d_in[1];
    const float* beta   = (const float*)d_in[2];
    const float* w_qkv  = (const float*)d_in[3];
    const float* w_out  = (const float*)d_in[4];
    const float* b_out  = (const float*)d_in[5];
    float* out = (float*)d_out;

    bf16 *xh,*xl,*wqh,*wql,*woh,*wol,*qh,*ql,*kh,*kl,*vh,*vl,*oh,*ol;
    cudaGetSymbolAddress((void**)&xh,  g_xn_hi);
    cudaGetSymbolAddress((void**)&xl,  g_xn_lo);
    cudaGetSymbolAddress((void**)&wqh, g_wqT_hi);
    cudaGetSymbolAddress((void**)&wql, g_wqT_lo);
    cudaGetSymbolAddress((void**)&woh, g_woT_hi);
    cudaGetSymbolAddress((void**)&wol, g_woT_lo);
    cudaGetSymbolAddress((void**)&qh,  g_q_hi);
    cudaGetSymbolAddress((void**)&ql,  g_q_lo);
    cudaGetSymbolAddress((void**)&kh,  g_k_hi);
    cudaGetSymbolAddress((void**)&kl,  g_k_lo);
    cudaGetSymbolAddress((void**)&vh,  g_v_hi);
    cudaGetSymbolAddress((void**)&vl,  g_v_lo);
    cudaGetSymbolAddress((void**)&oh,  g_o_hi);
    cudaGetSymbolAddress((void**)&ol,  g_o_lo);

    cudaFuncSetAttribute(gemm_mma_kernel<0>, cudaFuncAttributeMaxDynamicSharedMemorySize, GEMM_SMEM);
    cudaFuncSetAttribute(gemm_mma_kernel<1>, cudaFuncAttributeMaxDynamicSharedMemorySize, GEMM_SMEM);
    cudaFuncSetAttribute(attn_mma_kernel,    cudaFuncAttributeMaxDynamicSharedMemorySize, ATTN_SMEM);

    ln_split_kernel<<<ROWS, 256>>>(x, gamma, beta, xh, xl);
    transpose_split_kernel<<<dim3(NQKV/32, KD/32), dim3(32, 8)>>>(w_qkv, wqh, wql, KD, NQKV);
    transpose_split_kernel<<<dim3(DIM/32,  KD/32), dim3(32, 8)>>>(w_out, woh, wol, KD, DIM);
    gemm_mma_kernel<0><<<dim3(NQKV/128, ROWS/128), 256, GEMM_SMEM>>>(
        xh, xl, wqh, wql, qh, ql, kh, kl, vh, vl, nullptr, nullptr);
    attn_mma_kernel<<<dim3(NN/128, HH, BB), 256, ATTN_SMEM>>>(
        qh, ql, kh, kl, vh, vl, oh, ol);
    gemm_mma_kernel<1><<<dim3(DIM/128, ROWS/128), 256, GEMM_SMEM>>>(
        oh, ol, woh, wol, nullptr, nullptr, nullptr, nullptr, nullptr, nullptr, b_out, out);
}